// round 5
// baseline (speedup 1.0000x reference)
#include <cuda_runtime.h>
#include <cstdint>
#include <cstddef>

#define HID 512
#define SEQ 2048
#define BATCH 64
#define VOCAB 32000

// ---------------- scratch ----------------
__device__ float g_E[(size_t)VOCAB * HID];          // E' = embed @ W_ih0^T + biases
__device__ float g_ys[(size_t)SEQ * BATCH * HID];   // layer-0 outputs
__device__ float g_xb[(size_t)SEQ * BATCH * HID];   // layer-1 input term

// ---------------- helpers ----------------
__device__ __forceinline__ unsigned smem_u32(const void* p) {
    unsigned r;
    asm("{ .reg .u64 t; cvta.to.shared.u64 t, %1; cvt.u32.u64 %0, t; }" : "=r"(r) : "l"(p));
    return r;
}
__device__ __forceinline__ unsigned ctarank() {
    unsigned r; asm("mov.u32 %0, %%cluster_ctarank;" : "=r"(r)); return r;
}
__device__ __forceinline__ void cluster_sync() {
    asm volatile("barrier.cluster.arrive.aligned;" ::: "memory");
    asm volatile("barrier.cluster.wait.aligned;" ::: "memory");
}
__device__ __forceinline__ void fma2(unsigned long long& d, unsigned long long a, unsigned long long b) {
    asm("fma.rn.f32x2 %0, %1, %2, %0;" : "+l"(d) : "l"(a), "l"(b));
}
__device__ __forceinline__ unsigned long long pack2(float a) {
    unsigned long long r; asm("mov.b64 %0, {%1, %1};" : "=l"(r) : "f"(a)); return r;
}
__device__ __forceinline__ float sum2(unsigned long long a) {
    return __uint_as_float((unsigned)a) + __uint_as_float((unsigned)(a >> 32));
}
__device__ __forceinline__ float2 unpack2(unsigned long long a) {
    return make_float2(__uint_as_float((unsigned)a), __uint_as_float((unsigned)(a >> 32)));
}

// ---------------- GEMM: C[M][512] = A[M][512] @ W[512][512]^T + bi + bh ------
#define BM 128
#define BN 128
#define BK 16

__global__ void __launch_bounds__(256)
gemm_bias_kernel(const float* __restrict__ A, const float* __restrict__ W,
                 const float* __restrict__ bi, const float* __restrict__ bh,
                 float* __restrict__ C)
{
    __shared__ float As[BK][BM + 4];
    __shared__ float Bs[BK][BN + 4];

    int bm = blockIdx.x, bn = blockIdx.y;
    int tid = threadIdx.x;
    int tx = tid & 15, ty = tid >> 4;
    int ar = tid >> 2;
    int ac = (tid & 3) << 2;

    const float* Ap = A + (size_t)bm * BM * HID;
    const float* Wp = W + (size_t)bn * BN * HID;

    unsigned long long acc[8][4];
#pragma unroll
    for (int r = 0; r < 8; ++r)
#pragma unroll
        for (int c = 0; c < 4; ++c) acc[r][c] = 0ULL;

    for (int k0 = 0; k0 < HID; k0 += BK) {
        float4 a0 = *(const float4*)&Ap[(size_t)ar * HID + k0 + ac];
        float4 a1 = *(const float4*)&Ap[(size_t)(ar + 64) * HID + k0 + ac];
        float4 b0 = *(const float4*)&Wp[(size_t)ar * HID + k0 + ac];
        float4 b1 = *(const float4*)&Wp[(size_t)(ar + 64) * HID + k0 + ac];
        __syncthreads();
        As[ac + 0][ar] = a0.x; As[ac + 1][ar] = a0.y; As[ac + 2][ar] = a0.z; As[ac + 3][ar] = a0.w;
        As[ac + 0][ar + 64] = a1.x; As[ac + 1][ar + 64] = a1.y; As[ac + 2][ar + 64] = a1.z; As[ac + 3][ar + 64] = a1.w;
        Bs[ac + 0][ar] = b0.x; Bs[ac + 1][ar] = b0.y; Bs[ac + 2][ar] = b0.z; Bs[ac + 3][ar] = b0.w;
        Bs[ac + 0][ar + 64] = b1.x; Bs[ac + 1][ar + 64] = b1.y; Bs[ac + 2][ar + 64] = b1.z; Bs[ac + 3][ar + 64] = b1.w;
        __syncthreads();
#pragma unroll
        for (int k = 0; k < BK; ++k) {
            float4 av0 = *(const float4*)&As[k][ty * 4];
            float4 av1 = *(const float4*)&As[k][ty * 4 + 64];
            ulonglong2 bv0 = *(const ulonglong2*)&Bs[k][tx * 4];
            ulonglong2 bv1 = *(const ulonglong2*)&Bs[k][tx * 4 + 64];
            unsigned long long am[8];
            am[0] = pack2(av0.x); am[1] = pack2(av0.y); am[2] = pack2(av0.z); am[3] = pack2(av0.w);
            am[4] = pack2(av1.x); am[5] = pack2(av1.y); am[6] = pack2(av1.z); am[7] = pack2(av1.w);
#pragma unroll
            for (int r = 0; r < 8; ++r) {
                fma2(acc[r][0], am[r], bv0.x);
                fma2(acc[r][1], am[r], bv0.y);
                fma2(acc[r][2], am[r], bv1.x);
                fma2(acc[r][3], am[r], bv1.y);
            }
        }
    }

    int nb = bn * BN;
    float4 x0 = *(const float4*)&bi[nb + tx * 4];
    float4 y0 = *(const float4*)&bh[nb + tx * 4];
    float4 x1 = *(const float4*)&bi[nb + tx * 4 + 64];
    float4 y1 = *(const float4*)&bh[nb + tx * 4 + 64];
    float4 bias0 = make_float4(x0.x + y0.x, x0.y + y0.y, x0.z + y0.z, x0.w + y0.w);
    float4 bias1 = make_float4(x1.x + y1.x, x1.y + y1.y, x1.z + y1.z, x1.w + y1.w);
#pragma unroll
    for (int r = 0; r < 8; ++r) {
        int row_local = (r < 4) ? (ty * 4 + r) : (64 + ty * 4 + (r - 4));
        size_t row = (size_t)(bm * BM + row_local);
        float2 p0 = unpack2(acc[r][0]), p1 = unpack2(acc[r][1]);
        float2 p2 = unpack2(acc[r][2]), p3 = unpack2(acc[r][3]);
        float4 o0 = make_float4(p0.x + bias0.x, p0.y + bias0.y, p1.x + bias0.z, p1.y + bias0.w);
        float4 o1 = make_float4(p2.x + bias1.x, p2.y + bias1.y, p3.x + bias1.z, p3.y + bias1.w);
        *(float4*)&C[row * HID + nb + tx * 4] = o0;
        *(float4*)&C[row * HID + nb + tx * 4 + 64] = o1;
    }
}

// ---------------- recurrence: one layer, clusters of 8 CTAs ------------------
// Cluster owns 4 batch rows. CTA r holds W_hh rows [r*64, r*64+64) in smem,
// computes those 64 features for 4 batches each step, pushes the 256-float
// slice to all 8 CTAs via DSMEM; one cluster barrier per step.
#define REC_SW (64 * 516)
#define REC_SH (2 * 4 * 512)
#define REC_SP (16 * 64)
#define REC_SRC (4 * 2048)
#define REC_SMEM_BYTES ((REC_SW + REC_SH + REC_SP + REC_SRC) * 4)

__global__ void __cluster_dims__(8, 1, 1) __launch_bounds__(256, 1)
rnn_layer_kernel(const float* __restrict__ xterm,  // E' (layer0) or xb1 (layer1)
                 const int* __restrict__ src,      // tokens (layer0) or nullptr
                 const float* __restrict__ Whh,    // [512][512]
                 float* __restrict__ ys,           // [S][B][512] or nullptr
                 float* __restrict__ outh)         // [64][512] final hidden
{
    extern __shared__ float sm[];
    float* sW = sm;                      // [64][516]
    float* sH = sm + REC_SW;             // [2][4][512]
    float* sP = sH + REC_SH;             // [(ks*4+b)*64 + j]
    int* sSrc = (int*)(sP + REC_SP);     // [4][2048]

    const unsigned rank = ctarank();
    const int cid = blockIdx.x >> 3;
    const int gb0 = cid << 2;
    const int jbase = (int)rank << 6;
    const int tid = threadIdx.x;

    for (int idx = tid; idx < 64 * 128; idx += 256) {
        int jj = idx >> 7, kq = (idx & 127) << 2;
        *(float4*)&sW[jj * 516 + kq] = *(const float4*)&Whh[(size_t)(jbase + jj) * 512 + kq];
    }
    for (int idx = tid; idx < REC_SH; idx += 256) sH[idx] = 0.0f;
    if (src) {
        for (int idx = tid; idx < 4 * 2048; idx += 256)
            sSrc[idx] = src[(size_t)(gb0 + (idx >> 11)) * 2048 + (idx & 2047)];
    }
    __syncthreads();
    cluster_sync();

    const int j = tid & 63, ks = tid >> 6;
    const int fb = tid >> 6, fj = tid & 63;
    const float* wrow = &sW[j * 516 + ks * 128];

    for (int t = 0; t < SEQ; ++t) {
        const int cur = t & 1, nxt = cur ^ 1;
        float xv;
        if (src) {
            int tok = sSrc[(fb << 11) + t];
            xv = __ldg(&xterm[(size_t)tok * 512 + jbase + fj]);
        } else {
            xv = __ldg(&xterm[((size_t)t * 64 + gb0 + fb) * 512 + jbase + fj]);
        }

        const float* hb = &sH[cur * 2048 + ks * 128];
        unsigned long long a0 = 0, a1 = 0, a2 = 0, a3 = 0;
#pragma unroll 8
        for (int kk = 0; kk < 128; kk += 4) {
            ulonglong2 wq = *(const ulonglong2*)&wrow[kk];
            ulonglong2 h0 = *(const ulonglong2*)&hb[kk];
            ulonglong2 h1 = *(const ulonglong2*)&hb[512 + kk];
            ulonglong2 h2 = *(const ulonglong2*)&hb[1024 + kk];
            ulonglong2 h3 = *(const ulonglong2*)&hb[1536 + kk];
            fma2(a0, wq.x, h0.x); fma2(a0, wq.y, h0.y);
            fma2(a1, wq.x, h1.x); fma2(a1, wq.y, h1.y);
            fma2(a2, wq.x, h2.x); fma2(a2, wq.y, h2.y);
            fma2(a3, wq.x, h3.x); fma2(a3, wq.y, h3.y);
        }
        sP[(ks * 4 + 0) * 64 + j] = sum2(a0);
        sP[(ks * 4 + 1) * 64 + j] = sum2(a1);
        sP[(ks * 4 + 2) * 64 + j] = sum2(a2);
        sP[(ks * 4 + 3) * 64 + j] = sum2(a3);
        __syncthreads();

        float v = sP[(0 * 4 + fb) * 64 + fj] + sP[(1 * 4 + fb) * 64 + fj] +
                  sP[(2 * 4 + fb) * 64 + fj] + sP[(3 * 4 + fb) * 64 + fj];
        float h = tanhf(v + xv);

        unsigned laddr = smem_u32(&sH[nxt * 2048 + fb * 512 + jbase + fj]);
#pragma unroll
        for (int r = 0; r < 8; ++r) {
            asm volatile(
                "{ .reg .u32 ra; mapa.shared::cluster.u32 ra, %0, %1; "
                "st.shared::cluster.f32 [ra], %2; }"
                :: "r"(laddr), "r"(r), "f"(h) : "memory");
        }
        if (ys) ys[((size_t)t * 64 + gb0 + fb) * 512 + jbase + fj] = h;
        if (t == SEQ - 1) outh[(size_t)(gb0 + fb) * 512 + jbase + fj] = h;
        cluster_sync();
    }
}

// ---------------- launch ----------------
extern "C" void kernel_launch(void* const* d_in, const int* in_sizes, int n_in,
                              void* d_out, int out_size)
{
    const int* src = (const int*)d_in[0];
    const float* embed = (const float*)d_in[1];
    const float* W_ih = (const float*)d_in[2];   // [2][512][512]
    const float* W_hh = (const float*)d_in[3];   // [2][512][512]
    const float* b_ih = (const float*)d_in[4];   // [2][512]
    const float* b_hh = (const float*)d_in[5];   // [2][512]
    float* out = (float*)d_out;                  // [2][64][512]

    float *pE, *pYs, *pXb;
    cudaGetSymbolAddress((void**)&pE, g_E);
    cudaGetSymbolAddress((void**)&pYs, g_ys);
    cudaGetSymbolAddress((void**)&pXb, g_xb);

    cudaFuncSetAttribute(rnn_layer_kernel,
                         cudaFuncAttributeMaxDynamicSharedMemorySize, REC_SMEM_BYTES);

    // 1) E' = embed @ W_ih0^T + b_ih0 + b_hh0
    gemm_bias_kernel<<<dim3(VOCAB / BM, HID / BN), 256>>>(embed, W_ih, b_ih, b_hh, pE);
    // 2) layer-0 recurrence (gathers E'[src]), writes ys + final h
    rnn_layer_kernel<<<128, 256, REC_SMEM_BYTES>>>(pE, src, W_hh, pYs, out);
    // 3) xb1 = ys @ W_ih1^T + b_ih1 + b_hh1
    gemm_bias_kernel<<<dim3(SEQ * BATCH / BM, HID / BN), 256>>>(
        pYs, W_ih + (size_t)HID * HID, b_ih + HID, b_hh + HID, pXb);
    // 4) layer-1 recurrence, writes final h
    rnn_layer_kernel<<<128, 256, REC_SMEM_BYTES>>>(
        pXb, nullptr, W_hh + (size_t)HID * HID, nullptr, out + (size_t)BATCH * HID);
}